// round 16
// baseline (speedup 1.0000x reference)
#include <cuda_runtime.h>
#include <cuda_fp16.h>
#include <math.h>
#include <cstdint>

// Problem constants
#define EDIM   768
#define SDIM   256
#define BATCH  128
#define NROWS  (BATCH * SDIM)   // 32768
#define HDIM   (EDIM / 2)       // 384
#define NCLS   4
#define QW_SLICES 6
#define QW_ELEMS  (BATCH * EDIM)
#define NTILES_H2 (HDIM / 128)  // 3

// Scratch (static device globals — no allocation APIs allowed)
__device__ float    g_qW[QW_ELEMS];                         // q @ W1_top + b1 (fp32)
__device__ float    g_qWpart[QW_SLICES * QW_ELEMS];         // split-K partials
__device__ uint16_t g_segh[(size_t)NROWS * EDIM];           // segments fp16, 50 MB
__device__ uint16_t g_H1h[(size_t)NROWS * EDIM];            // fp16, 50 MB
__device__ uint16_t g_W1T[(size_t)EDIM * EDIM];             // W1 bottom, [N,K] fp16
__device__ uint16_t g_W2T[(size_t)HDIM * EDIM];             // W2 [N,K] fp16
__device__ float    g_lpart[NTILES_H2 * NROWS * NCLS];      // partial logits, 1.5 MB
__device__ float    g_preds[NROWS * NCLS];

__device__ __forceinline__ float gelu_exact(float x) {
    return 0.5f * x * (1.0f + erff(x * 0.70710678118654752f));
}

__device__ __forceinline__ uint32_t smem_u32(const void* p) {
    uint32_t a;
    asm("{ .reg .u64 t; cvta.to.shared.u64 t, %1; cvt.u32.u64 %0, t; }" : "=r"(a) : "l"(p));
    return a;
}
__device__ __forceinline__ void cp16(uint32_t saddr, const void* g) {
    asm volatile("cp.async.cg.shared.global [%0], [%1], 16;" :: "r"(saddr), "l"(g));
}
#define CP_COMMIT() asm volatile("cp.async.commit_group;" ::: "memory")
#define CP_WAIT2()  asm volatile("cp.async.wait_group 2;"  ::: "memory")
#define CP_WAIT0()  asm volatile("cp.async.wait_group 0;"  ::: "memory")

__device__ __forceinline__ void ldsm_x4(uint32_t* r, uint32_t addr) {
    asm volatile("ldmatrix.sync.aligned.m8n8.x4.shared.b16 {%0,%1,%2,%3}, [%4];"
                 : "=r"(r[0]), "=r"(r[1]), "=r"(r[2]), "=r"(r[3]) : "r"(addr));
}
// fp16 tensor-core mma: D[16x8] += A[16x16] * B[16x8], fp32 accumulate.
__device__ __forceinline__ void mma_f16(float* d, const uint32_t* a, const uint32_t* b) {
    asm volatile(
        "mma.sync.aligned.m16n8k16.row.col.f32.f16.f16.f32 "
        "{%0,%1,%2,%3}, {%4,%5,%6,%7}, {%8,%9}, {%0,%1,%2,%3};\n"
        : "+f"(d[0]), "+f"(d[1]), "+f"(d[2]), "+f"(d[3])
        : "r"(a[0]), "r"(a[1]), "r"(a[2]), "r"(a[3]), "r"(b[0]), "r"(b[1]));
}

// ---------------------------------------------------------------------------
// fp16 tensor-core GEMM, 4-stage cp.async pipeline, HIGH-OCCUPANCY geometry:
// 512 threads (16 warps, 4m x 4n grid), warp tile 32x32, mma m16n8k16,
// single-buffered fragments, <=64 regs/thread -> 2 CTAs/SM = 32 warps/SM.
// Tile rows: 16 data + 4 pad = 20 words (LDSM conflict-free).
// Dynamic smem: 4 stages x 20480 B = 81920 B. Per chunk each thread issues
// exactly 1 cp16 for A and 1 for B.
// EPI 1: gelu(x + extra[(row>>8)*EDIM + col]) -> fp16 C     (qW add; gemm1)
// EPI 2: gelu(x + extra[col]) -> partial logits via W3 -> lpart   (gemm2)
// All dims divide tiles exactly; K/32 >= 3.
// ---------------------------------------------------------------------------
template <int EPI>
__global__ void __launch_bounds__(512, 2) gemm_h(
    const uint16_t* __restrict__ A, const uint16_t* __restrict__ BT,
    uint16_t* __restrict__ C, const float* __restrict__ extra,
    const float* __restrict__ W3, float* __restrict__ lpart,
    int M, int N, int K)
{
    constexpr int BM = 128, BK = 32;
    constexpr int STRIDE = BK / 2 + 4;                 // 20 words/row
    constexpr int TILEB = BM * STRIDE * 4;             // 10240 bytes per tile
    constexpr int STAGEB = 2 * TILEB;                  // 20480 bytes per stage
    constexpr int ROWB16 = 16 * STRIDE * 4;            // 16 rows, bytes
    extern __shared__ uint32_t smem[];

    const int bm = blockIdx.y * BM;
    const int bn = blockIdx.x * BM;
    const int tid = threadIdx.x, warp = tid >> 5, lane = tid & 31;
    const int gid = lane >> 2;            // 0..7
    const int tig = lane & 3;             // 0..3
    const int mwarp = (warp >> 2) * 32;   // 0,32,64,96
    const int nwarp = (warp & 3) * 32;    // 0,32,64,96

    const uint32_t sb = smem_u32(smem);

    // Per-chunk fill: 1 cp16 into A + 1 into B per thread (512 x 16B each tile)
    const int fr = tid >> 2;              // 0..127 (row)
    const int fq = tid & 3;               // 16B group in row
    const uint16_t* Abase = A + (size_t)bm * K;
    const uint16_t* Bbase = BT + (size_t)bn * K;
    const uint32_t fill_d = (fr * STRIDE + fq * 4) * 4;
    const size_t   fill_g = (size_t)fr * K + fq * 8;

    const uint32_t a_off = ((mwarp + (lane & 15)) * STRIDE + ((lane & 16) ? 4 : 0)) * 4;
    const uint32_t b_off = TILEB + ((nwarp + ((lane & 16) ? 8 : 0) + (lane & 7)) * STRIDE
                            + ((lane & 8) ? 4 : 0)) * 4;

    float acc[2][4][4];
    #pragma unroll
    for (int mt = 0; mt < 2; mt++)
        #pragma unroll
        for (int nt = 0; nt < 4; nt++)
            #pragma unroll
            for (int r = 0; r < 4; r++) acc[mt][nt][r] = 0.0f;

    const int nkc = K / BK;

    // prologue: chunks 0,1,2 into stages 0,1,2
    #pragma unroll
    for (int pc = 0; pc < 3; pc++) {
        uint32_t st = sb + pc * STAGEB;
        cp16(st + fill_d, Abase + pc * BK + fill_g);
        cp16(st + TILEB + fill_d, Bbase + pc * BK + fill_g);
        CP_COMMIT();
    }

    int s = 0;   // stage of current chunk
    for (int kc = 0; kc < nkc; kc++) {
        CP_WAIT2();          // chunk kc landed (kc+1, kc+2 may be in flight)
        __syncthreads();     // all warps done with stage being refilled

        if (kc + 3 < nkc) {
            uint32_t st = sb + ((s + 3) & 3) * STAGEB;
            cp16(st + fill_d, Abase + (kc + 3) * BK + fill_g);
            cp16(st + TILEB + fill_d, Bbase + (kc + 3) * BK + fill_g);
        }
        CP_COMMIT();         // one group per iteration (possibly empty)

        const uint32_t abase = sb + s * STAGEB + a_off;
        const uint32_t bbase = sb + s * STAGEB + b_off;
        #pragma unroll
        for (int ks = 0; ks < 2; ks++) {
            const uint32_t ko = ks * 32;
            uint32_t af[2][4];
            ldsm_x4(af[0], abase + ko);
            ldsm_x4(af[1], abase + ROWB16 + ko);
            uint32_t bf[4][2];
            ldsm_x4(&bf[0][0], bbase + ko);             // nt0, nt1
            ldsm_x4(&bf[2][0], bbase + ROWB16 + ko);    // nt2, nt3
            #pragma unroll
            for (int mt = 0; mt < 2; mt++)
                #pragma unroll
                for (int nt = 0; nt < 4; nt++)
                    mma_f16(acc[mt][nt], af[mt], bf[nt]);
        }
        s = (s + 1) & 3;
    }

    if (EPI == 1) {
        // ---- gemm1 epilogue: qW add + gelu -> fp16 C ----
        #pragma unroll
        for (int mt = 0; mt < 2; mt++) {
            #pragma unroll
            for (int nt = 0; nt < 4; nt++) {
                int r0 = bm + mwarp + mt * 16 + gid;
                int r1 = r0 + 8;
                int c  = bn + nwarp + nt * 8 + 2 * tig;
                const float* ex0 = extra + (r0 >> 8) * EDIM;
                const float* ex1 = extra + (r1 >> 8) * EDIM;
                float v0 = gelu_exact(acc[mt][nt][0] + ex0[c]);
                float v1 = gelu_exact(acc[mt][nt][1] + ex0[c + 1]);
                float v2 = gelu_exact(acc[mt][nt][2] + ex1[c]);
                float v3 = gelu_exact(acc[mt][nt][3] + ex1[c + 1]);
                __half2 h01 = __floats2half2_rn(v0, v1);
                __half2 h23 = __floats2half2_rn(v2, v3);
                *(uint32_t*)(C + (size_t)r0 * N + c) = *(uint32_t*)&h01;
                *(uint32_t*)(C + (size_t)r1 * N + c) = *(uint32_t*)&h23;
            }
        }
    } else {
        // ---- gemm2 epilogue: bias + gelu, then partial logits via W3 ----
        float pl0[2][4], pl1[2][4];      // [mt][cls]
        #pragma unroll
        for (int mt = 0; mt < 2; mt++)
            #pragma unroll
            for (int k = 0; k < 4; k++) { pl0[mt][k] = 0.f; pl1[mt][k] = 0.f; }

        #pragma unroll
        for (int mt = 0; mt < 2; mt++) {
            #pragma unroll
            for (int nt = 0; nt < 4; nt++) {
                int c  = bn + nwarp + nt * 8 + 2 * tig;
                float e0 = extra[c], e1 = extra[c + 1];
                float v0 = gelu_exact(acc[mt][nt][0] + e0);
                float v1 = gelu_exact(acc[mt][nt][1] + e1);
                float v2 = gelu_exact(acc[mt][nt][2] + e0);
                float v3 = gelu_exact(acc[mt][nt][3] + e1);
                float4 w0 = *(const float4*)(W3 + (size_t)c * NCLS);
                float4 w1 = *(const float4*)(W3 + (size_t)(c + 1) * NCLS);
                pl0[mt][0] = fmaf(v0, w0.x, fmaf(v1, w1.x, pl0[mt][0]));
                pl0[mt][1] = fmaf(v0, w0.y, fmaf(v1, w1.y, pl0[mt][1]));
                pl0[mt][2] = fmaf(v0, w0.z, fmaf(v1, w1.z, pl0[mt][2]));
                pl0[mt][3] = fmaf(v0, w0.w, fmaf(v1, w1.w, pl0[mt][3]));
                pl1[mt][0] = fmaf(v2, w0.x, fmaf(v3, w1.x, pl1[mt][0]));
                pl1[mt][1] = fmaf(v2, w0.y, fmaf(v3, w1.y, pl1[mt][1]));
                pl1[mt][2] = fmaf(v2, w0.z, fmaf(v3, w1.z, pl1[mt][2]));
                pl1[mt][3] = fmaf(v2, w0.w, fmaf(v3, w1.w, pl1[mt][3]));
            }
        }
        // quad reduce over tig
        #pragma unroll
        for (int d = 1; d <= 2; d <<= 1) {
            #pragma unroll
            for (int mt = 0; mt < 2; mt++)
                #pragma unroll
                for (int k = 0; k < 4; k++) {
                    pl0[mt][k] += __shfl_xor_sync(0xffffffffu, pl0[mt][k], d);
                    pl1[mt][k] += __shfl_xor_sync(0xffffffffu, pl1[mt][k], d);
                }
        }
        // cross-warp reduce via smem (reuse pipeline stages; all cp.async done)
        CP_WAIT0();
        __syncthreads();
        float* red = (float*)smem;        // [4 nwarp][128 row][4 cls] = 8 KB
        if (tig == 0) {
            int nw = warp & 3;
            #pragma unroll
            for (int mt = 0; mt < 2; mt++) {
                int row0 = (warp >> 2) * 32 + mt * 16 + gid;
                *(float4*)&red[((nw * 128) + row0) * 4]     =
                    make_float4(pl0[mt][0], pl0[mt][1], pl0[mt][2], pl0[mt][3]);
                *(float4*)&red[((nw * 128) + row0 + 8) * 4] =
                    make_float4(pl1[mt][0], pl1[mt][1], pl1[mt][2], pl1[mt][3]);
            }
        }
        __syncthreads();
        if (tid < 128) {
            float4 s0 = *(float4*)&red[((0 * 128) + tid) * 4];
            float4 s1 = *(float4*)&red[((1 * 128) + tid) * 4];
            float4 s2 = *(float4*)&red[((2 * 128) + tid) * 4];
            float4 s3 = *(float4*)&red[((3 * 128) + tid) * 4];
            float4 t = make_float4(s0.x + s1.x + s2.x + s3.x,
                                   s0.y + s1.y + s2.y + s3.y,
                                   s0.z + s1.z + s2.z + s3.z,
                                   s0.w + s1.w + s2.w + s3.w);
            *(float4*)&lpart[((size_t)blockIdx.x * NROWS + bm + tid) * NCLS] = t;
        }
    }
}

// ======================= logits combine + softmax ===========================
__global__ void logits_combine_k(const float* __restrict__ lpart,
                                 const float* __restrict__ b3,
                                 float* __restrict__ preds)
{
    int i = blockIdx.x * blockDim.x + threadIdx.x;
    if (i >= NROWS) return;
    float4 a = *(const float4*)&lpart[(size_t)(0 * NROWS + i) * NCLS];
    float4 b = *(const float4*)&lpart[(size_t)(1 * NROWS + i) * NCLS];
    float4 c = *(const float4*)&lpart[(size_t)(2 * NROWS + i) * NCLS];
    float l0 = a.x + b.x + c.x + b3[0];
    float l1 = a.y + b.y + c.y + b3[1];
    float l2 = a.z + b.z + c.z + b3[2];
    float l3 = a.w + b.w + c.w + b3[3];
    float mx = fmaxf(fmaxf(l0, l1), fmaxf(l2, l3));
    float e0 = expf(l0 - mx), e1 = expf(l1 - mx), e2 = expf(l2 - mx), e3 = expf(l3 - mx);
    float inv = 1.0f / (e0 + e1 + e2 + e3);
    *(float4*)&preds[(size_t)i * NCLS] = make_float4(e0 * inv, e1 * inv, e2 * inv, e3 * inv);
}

// ======================= fp32 -> fp16 bulk convert (16B stores) =============
__global__ void f2h_k(const float* __restrict__ src, uint16_t* __restrict__ dst, int n8)
{
    int i = blockIdx.x * blockDim.x + threadIdx.x;
    if (i >= n8) return;
    float4 v0 = ((const float4*)src)[2 * i];
    float4 v1 = ((const float4*)src)[2 * i + 1];
    __half2 h0 = __floats2half2_rn(v0.x, v0.y);
    __half2 h1 = __floats2half2_rn(v0.z, v0.w);
    __half2 h2 = __floats2half2_rn(v1.x, v1.y);
    __half2 h3 = __floats2half2_rn(v1.z, v1.w);
    ((uint4*)dst)[i] = make_uint4(*(uint32_t*)&h0, *(uint32_t*)&h1,
                                  *(uint32_t*)&h2, *(uint32_t*)&h3);
}

// ======================= tiled weight transpose + fp16 ======================
__global__ void transposeW_t(const float* __restrict__ src, uint16_t* __restrict__ dst,
                             int K, int N)
{
    __shared__ float t[32][33];
    int n0 = blockIdx.x * 32, k0 = blockIdx.y * 32;
    int tx = threadIdx.x & 31, ty = threadIdx.x >> 5;
    #pragma unroll
    for (int j = 0; j < 32; j += 8)
        t[ty + j][tx] = src[(size_t)(k0 + ty + j) * N + n0 + tx];
    __syncthreads();
    #pragma unroll
    for (int j = 0; j < 32; j += 8) {
        __half h = __float2half(t[tx][ty + j]);
        dst[(size_t)(n0 + ty + j) * K + k0 + tx] = *(uint16_t*)&h;
    }
}

// ======================= qW precompute (split-K tf32 mma) ===================
__device__ __forceinline__ unsigned f2tf32(float x) {
    unsigned r;
    asm("cvt.rna.tf32.f32 %0, %1;" : "=r"(r) : "f"(x));
    return r;
}
__device__ __forceinline__ void mma_tf32(float* d, const unsigned* a, const unsigned* b) {
    asm volatile(
        "mma.sync.aligned.m16n8k8.row.col.f32.tf32.tf32.f32 "
        "{%0,%1,%2,%3}, {%4,%5,%6,%7}, {%8,%9}, {%0,%1,%2,%3};\n"
        : "+f"(d[0]), "+f"(d[1]), "+f"(d[2]), "+f"(d[3])
        : "r"(a[0]), "r"(a[1]), "r"(a[2]), "r"(a[3]), "r"(b[0]), "r"(b[1]));
}

__global__ void __launch_bounds__(256) qw_gemm_splitk(
    const float* __restrict__ A, const float* __restrict__ B,
    float* __restrict__ parts, int N, int K)
{
    constexpr int BM = 128, BN = 128, BK = 32, KSLICE = 128;
    constexpr int APAD = 36, BPAD = 136;
    __shared__ unsigned As[BM * APAD];
    __shared__ unsigned Bs[BK * BPAD];

    const int bn = blockIdx.x * BN;
    const int kbeg = blockIdx.z * KSLICE;
    float* Cout = parts + (size_t)blockIdx.z * QW_ELEMS;

    const int tid = threadIdx.x, warp = tid >> 5, lane = tid & 31;
    const int gid = lane >> 2, tig = lane & 3;
    const int mwarp = (warp >> 2) * 64, nwarp = (warp & 3) * 32;

    float acc[4][4][4];
    #pragma unroll
    for (int mt = 0; mt < 4; mt++)
        #pragma unroll
        for (int nt = 0; nt < 4; nt++)
            #pragma unroll
            for (int r = 0; r < 4; r++) acc[mt][nt][r] = 0.0f;

    const float* Bptr = B + bn;
    for (int k0 = kbeg; k0 < kbeg + KSLICE; k0 += BK) {
        #pragma unroll
        for (int i = 0; i < 4; i++) {
            int idx = tid + i * 256;
            int ar = idx >> 3, kq = (idx & 7) * 4;
            float4 v = *(const float4*)(A + (size_t)ar * K + k0 + kq);
            unsigned* dst = &As[ar * APAD + kq];
            dst[0] = f2tf32(v.x); dst[1] = f2tf32(v.y);
            dst[2] = f2tf32(v.z); dst[3] = f2tf32(v.w);
        }
        #pragma unroll
        for (int i = 0; i < 4; i++) {
            int idx = tid + i * 256;
            int bk = idx >> 5, nq = (idx & 31) * 4;
            float4 v = *(const float4*)(Bptr + (size_t)(k0 + bk) * N + nq);
            unsigned* dst = &Bs[bk * BPAD + nq];
            dst[0] = f2tf32(v.x); dst[1] = f2tf32(v.y);
            dst[2] = f2tf32(v.z); dst[3] = f2tf32(v.w);
        }
        __syncthreads();
        #pragma unroll
        for (int ks = 0; ks < BK / 8; ks++) {
            const int k = ks * 8;
            unsigned af[4][4];
            #pragma unroll
            for (int mt = 0; mt < 4; mt++) {
                int m = mwarp + mt * 16;
                af[mt][0] = As[(m + gid)     * APAD + k + tig];
                af[mt][1] = As[(m + gid + 8) * APAD + k + tig];
                af[mt][2] = As[(m + gid)     * APAD + k + tig + 4];
                af[mt][3] = As[(m + gid + 8) * APAD + k + tig + 4];
            }
            unsigned bf[4][2];
            #pragma unroll
            for (int nt = 0; nt < 4; nt++) {
                int n = nwarp + nt * 8;
                bf[nt][0] = Bs[(k + tig)     * BPAD + n + gid];
                bf[nt][1] = Bs[(k + tig + 4) * BPAD + n + gid];
            }
            #pragma unroll
            for (int mt = 0; mt < 4; mt++)
                #pragma unroll
                for (int nt = 0; nt < 4; nt++)
                    mma_tf32(acc[mt][nt], af[mt], bf[nt]);
        }
        __syncthreads();
    }
    #pragma unroll
    for (int mt = 0; mt < 4; mt++)
        #pragma unroll
        for (int nt = 0; nt < 4; nt++) {
            int r0 = mwarp + mt * 16 + gid;
            int r1 = r0 + 8;
            int c  = bn + nwarp + nt * 8 + 2 * tig;
            *(float2*)(Cout + (size_t)r0 * N + c) =
                make_float2(acc[mt][nt][0], acc[mt][nt][1]);
            *(float2*)(Cout + (size_t)r1 * N + c) =
                make_float2(acc[mt][nt][2], acc[mt][nt][3]);
        }
}

__global__ void qw_reduce_k(const float* __restrict__ parts, const float* __restrict__ b1,
                            float* __restrict__ qW)
{
    int i = blockIdx.x * blockDim.x + threadIdx.x;
    if (i >= QW_ELEMS) return;
    float s = b1[i % EDIM];
    #pragma unroll
    for (int p = 0; p < QW_SLICES; p++) s += parts[p * QW_ELEMS + i];
    qW[i] = s;
}

// ======================= per-bag aggregation ================================
__global__ void aggregate_k(const float* __restrict__ preds,
                            const int* __restrict__ nseg,
                            float* __restrict__ out)
{
    int b = blockIdx.x;
    int c = threadIdx.x;
    __shared__ float ss[NCLS][SDIM];
    __shared__ float suf[NCLS][SDIM];
    if (c >= NCLS) return;

    int n = nseg[b];
    const float4* p = (const float4*)(preds + (size_t)b * SDIM * NCLS);

    for (int i = 0; i < n; i++) {
        float4 pv = p[i];
        float sv = (c == 0) ? 0.0f
                 : (c == 1) ? pv.x
                 : (c == 2) ? pv.x + pv.y
                            : pv.x + pv.y + pv.z;
        ss[c][i] = sv;
    }
    float r = 1.0f;
    for (int i = n - 1; i >= 0; i--) {
        suf[c][i] = r;
        r *= ss[c][i];
    }
    float pre = 1.0f, cpl = 1.0f, sum = 0.0f, prodp = 1.0f;
    for (int i = 0; i < n; i++) {
        float4 pv = p[i];
        float pc = (c == 0) ? pv.x : (c == 1) ? pv.y : (c == 2) ? pv.z : pv.w;
        float L = pre * suf[c][i];
        cpl *= L;
        sum = fmaf(pc, cpl, sum);
        prodp *= pc;
        pre *= ss[c][i];
    }
    out[b * NCLS + c] = sum * 0.25f + prodp;
}

// ===========================================================================
extern "C" void kernel_launch(void* const* d_in, const int* in_sizes, int n_in,
                              void* d_out, int out_size)
{
    const float* questions = (const float*)d_in[0];
    const float* segments  = (const float*)d_in[1];
    const float* W1        = (const float*)d_in[2];
    const float* b1        = (const float*)d_in[3];
    const float* W2        = (const float*)d_in[4];
    const float* b2        = (const float*)d_in[5];
    const float* W3        = (const float*)d_in[6];
    const float* b3        = (const float*)d_in[7];
    const int*   nseg      = (const int*)d_in[8];
    float* out = (float*)d_out;

    float *pqW, *pqWpart, *plpart, *ppreds;
    uint16_t *psegh, *pH1h, *pW1T, *pW2T;
    cudaGetSymbolAddress((void**)&pqW,     g_qW);
    cudaGetSymbolAddress((void**)&pqWpart, g_qWpart);
    cudaGetSymbolAddress((void**)&psegh,   g_segh);
    cudaGetSymbolAddress((void**)&pH1h,    g_H1h);
    cudaGetSymbolAddress((void**)&pW1T,    g_W1T);
    cudaGetSymbolAddress((void**)&pW2T,    g_W2T);
    cudaGetSymbolAddress((void**)&plpart,  g_lpart);
    cudaGetSymbolAddress((void**)&ppreds,  g_preds);

    constexpr int GEMM_SMEM = 4 * 2 * 128 * 20 * 4;   // 81920 B
    cudaFuncSetAttribute(gemm_h<1>, cudaFuncAttributeMaxDynamicSharedMemorySize, GEMM_SMEM);
    cudaFuncSetAttribute(gemm_h<2>, cudaFuncAttributeMaxDynamicSharedMemorySize, GEMM_SMEM);

    // 0a) segments -> fp16
    f2h_k<<<((size_t)NROWS * EDIM / 8 + 255) / 256, 256>>>(
        segments, psegh, NROWS * EDIM / 8);
    // 0b) weight transpose + fp16 convert (tiled)
    transposeW_t<<<dim3(EDIM / 32, EDIM / 32), 256>>>(W1 + (size_t)EDIM * EDIM, pW1T, EDIM, EDIM);
    transposeW_t<<<dim3(HDIM / 32, EDIM / 32), 256>>>(W2, pW2T, EDIM, HDIM);

    // 1) qW = q @ W1_top + b1: split-K over 6 slices + deterministic reduce
    qw_gemm_splitk<<<dim3(EDIM / 128, 1, QW_SLICES), 256>>>(
        questions, W1, pqWpart, EDIM, EDIM);
    qw_reduce_k<<<(QW_ELEMS + 255) / 256, 256>>>(pqWpart, b1, pqW);

    // 2) H1h = gelu(seg @ W1_botT^T + qW[b])
    gemm_h<1><<<dim3(EDIM / 128, NROWS / 128), 512, GEMM_SMEM>>>(
        psegh, pW1T, pH1h, pqW, nullptr, nullptr, NROWS, EDIM, EDIM);

    // 3) partial logits = gelu(H1h @ W2T^T + b2) @ W3   (fused epilogue)
    gemm_h<2><<<dim3(HDIM / 128, NROWS / 128), 512, GEMM_SMEM>>>(
        pH1h, pW2T, nullptr, b2, W3, plpart, NROWS, HDIM, EDIM);

    // 4) preds = softmax(sum partials + b3)
    logits_combine_k<<<(NROWS + 255) / 256, 256>>>(plpart, b3, ppreds);

    // 5) per-bag aggregation
    aggregate_k<<<BATCH, 32>>>(ppreds, nseg, out);
}